// round 8
// baseline (speedup 1.0000x reference)
#include <cuda_runtime.h>
#include <math.h>

// ---------------------------------------------------------------------------
// MS-SSIM, 5 levels, 16x3x512x512 fp32 (48 planes). 3 launches:
//   ssim_level0 (fused full pool pyramid L1..L4),
//   ssim_rest   (levels 1..4 in one grid),
//   final       (parallel weighted combine; re-zeros d_sums for next call).
// Blur: 2 packed f32x2 streams (x,y) and (x^2+y^2, x*y), 4 outputs/thread,
// all 256 threads active. All SMEM access 128-bit:
//   - hblur reads sIN as ulonglong2 (7 LDS.128 / item)
//   - h-blurred maps interleaved {MU,SP} -> STS.128 writes, LDS.128 reads
// ---------------------------------------------------------------------------

typedef unsigned long long u64;

__device__ __forceinline__ u64 pack2(float lo, float hi) {
    u64 r; asm("mov.b64 %0,{%1,%2};" : "=l"(r) : "f"(lo), "f"(hi)); return r;
}
__device__ __forceinline__ void unpack2(u64 v, float& lo, float& hi) {
    asm("mov.b64 {%0,%1},%2;" : "=f"(lo), "=f"(hi) : "l"(v));
}
__device__ __forceinline__ u64 fma2(u64 a, u64 b, u64 c) {
    u64 d; asm("fma.rn.f32x2 %0,%1,%2,%3;" : "=l"(d) : "l"(a), "l"(b), "l"(c)); return d;
}
__device__ __forceinline__ u64 mul2(u64 a, u64 b) {
    u64 d; asm("mul.rn.f32x2 %0,%1,%2;" : "=l"(d) : "l"(a), "l"(b)); return d;
}
__device__ __forceinline__ u64 add2(u64 a, u64 b) {
    u64 d; asm("add.rn.f32x2 %0,%1,%2;" : "=l"(d) : "l"(a), "l"(b)); return d;
}
__device__ __forceinline__ float sqrt_fast(float x) {
    float r; asm("sqrt.approx.f32 %0,%1;" : "=f"(r) : "f"(x)); return r;
}

#define TW 32
#define TH 32
#define EH 42
#define EW 42
#define SIN_S 44       // EVEN u64 stride -> 16B-aligned ulonglong2 access
#define SH_S  33       // logical (r,c) stride of interleaved h-blur maps

// gaussian(sigma=1.5, 11 taps), normalized
#define G_0 0.00102838f
#define G_1 0.00759876f
#define G_2 0.03600088f
#define G_3 0.10936090f
#define G_4 0.21300530f
#define G_5 0.26601160f
#define GQ(t) G2c[(t) < 6 ? (t) : 10 - (t)]

// pooled pyramids (levels 1..4), 48 planes each
__device__ __align__(16) float d_Xp[4177920];
__device__ __align__(16) float d_Yp[4177920];
__device__ float d_sums[480];   // [level][img][2]  (zero-init; final re-zeros)

#define OFF1 0
#define OFF2 3145728
#define OFF3 3932160
#define OFF4 4128768

// accumulate tap t for value pair (v, sp) into 4 sliding accumulators
#define HTAP(k)                                                        \
    do {                                                               \
        _Pragma("unroll")                                              \
        for (int q = 0; q < 4; q++) {                                  \
            int t = (k) - q;                                           \
            if (t >= 0 && t < 11) {                                    \
                aMU[q] = fma2(v, GQ(t), aMU[q]);                       \
                aSP[q] = fma2(sp, GQ(t), aSP[q]);                      \
            }                                                          \
        }                                                              \
    } while (0)

// core tile worker. POOL => level 0 (H=512, also emits L1..L4 pyramid).
template <bool POOL>
__device__ __forceinline__ void ssim_tile(
    const float* __restrict__ Xi, const float* __restrict__ Yi,
    int H, int level, int img, int bx, int by,
    float* __restrict__ Xp, float* __restrict__ Yp)
{
    __shared__ u64 sIN[EH * SIN_S];                      // packed (x,y)
    __shared__ __align__(16) u64 sHB[EH * SH_S * 2];     // interleaved {MU,SP}
    __shared__ u64 sL2[64];
    __shared__ float red[2][8];

    const int W = H;
    const int outH = H - 10;
    const int tx0 = bx * TW;
    const int ty0 = by * TH;
    const int tid = threadIdx.x;

    const u64 G2c[6] = {pack2(G_0,G_0), pack2(G_1,G_1), pack2(G_2,G_2),
                        pack2(G_3,G_3), pack2(G_4,G_4), pack2(G_5,G_5)};

    // ---- load extended tile, packed (x,y) -----------------------------------
    const bool interior = (tx0 + EW <= W) && (ty0 + EH <= H);
    if (interior) {
        // 42 rows x 21 col-pairs; float2 global loads + one 16B SMEM store
        for (int i = tid; i < EH * (EW / 2); i += 256) {
            int r = i / 21, c2 = i - r * 21;
            int c = c2 * 2;
            const float2 lx = *(const float2*)(Xi + (size_t)(ty0 + r) * W + tx0 + c);
            const float2 ly = *(const float2*)(Yi + (size_t)(ty0 + r) * W + tx0 + c);
            ulonglong2 v;
            v.x = pack2(lx.x, ly.x);
            v.y = pack2(lx.y, ly.y);
            *(ulonglong2*)&sIN[r * SIN_S + c] = v;
        }
    } else {
        for (int i = tid; i < EH * EW; i += 256) {
            int r2 = i / EW, c2 = i - r2 * EW;
            int gr = ty0 + r2; if (gr > H - 1) gr = H - 1;
            int gc = tx0 + c2; if (gc > W - 1) gc = W - 1;
            sIN[r2 * SIN_S + c2] = pack2(Xi[(size_t)gr * W + gc], Yi[(size_t)gr * W + gc]);
        }
    }
    __syncthreads();

    // ---- fused pool pyramid (level 0 only): L1, L2 --------------------------
    if (POOL) {
        const u64 QUARTER = pack2(0.25f, 0.25f);
        const int lane = tid & 31;
        int ph = tid >> 4, pw = tid & 15;
        const u64* p0 = sIN + (ph * 2) * SIN_S + pw * 2;
        u64 v1 = mul2(add2(add2(p0[0], p0[1]), add2(p0[SIN_S], p0[SIN_S + 1])), QUARTER);
        {
            float a, b; unpack2(v1, a, b);
            size_t po = (size_t)img * 65536 + (size_t)(by * 16 + ph) * 256 + (bx * 16 + pw);
            (Xp + OFF1)[po] = a; (Yp + OFF1)[po] = b;
        }
        u64 s2 = add2(v1, __shfl_xor_sync(0xffffffffu, v1, 1));
        s2 = add2(s2, __shfl_xor_sync(0xffffffffu, s2, 16));
        if ((lane & 17) == 0) {
            u64 v2 = mul2(s2, QUARTER);
            int qh = tid >> 5, qw = lane >> 1;
            float a, b; unpack2(v2, a, b);
            size_t po = (size_t)img * 16384 + (size_t)(by * 8 + qh) * 128 + (bx * 8 + qw);
            (Xp + OFF2)[po] = a; (Yp + OFF2)[po] = b;
            sL2[qh * 8 + qw] = v2;
        }
    }

    // ---- horizontal blur: 42 rows x 8 col-groups (4 outputs each) -----------
    {
        auto hblur = [&](int item) {
            int r = item >> 3, c4 = (item & 7) << 2;
            const u64* row = sIN + r * SIN_S + c4;    // 16B aligned (44 even, c4%4==0)
            u64 aMU[4] = {0,0,0,0}, aSP[4] = {0,0,0,0};
#pragma unroll
            for (int kk = 0; kk < 7; kk++) {
                ulonglong2 vv = *(const ulonglong2*)&row[kk * 2];
                {
                    u64 v = vv.x;
                    float vx, vy; unpack2(v, vx, vy);
                    u64 sp = pack2(fmaf(vx, vx, vy * vy), vx * vy);
                    HTAP(kk * 2);
                }
                {
                    u64 v = vv.y;
                    float vx, vy; unpack2(v, vx, vy);
                    u64 sp = pack2(fmaf(vx, vx, vy * vy), vx * vy);
                    HTAP(kk * 2 + 1);
                }
            }
            int o = (r * SH_S + c4) * 2;
#pragma unroll
            for (int q = 0; q < 4; q++) {
                ulonglong2 w; w.x = aMU[q]; w.y = aSP[q];
                *(ulonglong2*)&sHB[o + q * 2] = w;
            }
        };
        hblur(tid);
        if (tid < EH * 8 - 256) hblur(tid + 256);
    }
    __syncthreads();

    // ---- pyramid tail: L3 + L4 -----------------------------------------------
    if (POOL && tid < 16) {
        const u64 QUARTER = pack2(0.25f, 0.25f);
        int rh = tid >> 2, rw = tid & 3;
        const u64* q0 = sL2 + (rh * 2) * 8 + rw * 2;
        u64 v3 = mul2(add2(add2(q0[0], q0[1]), add2(q0[8], q0[9])), QUARTER);
        {
            float a, b; unpack2(v3, a, b);
            size_t po = (size_t)img * 4096 + (size_t)(by * 4 + rh) * 64 + (bx * 4 + rw);
            (Xp + OFF3)[po] = a; (Yp + OFF3)[po] = b;
        }
        u64 s4 = add2(v3, __shfl_xor_sync(0xffffu, v3, 1));
        s4 = add2(s4, __shfl_xor_sync(0xffffu, s4, 4));
        if ((tid & 5) == 0) {
            u64 v4 = mul2(s4, QUARTER);
            int sh = tid >> 3, sw = (tid >> 1) & 1;
            float a, b; unpack2(v4, a, b);
            size_t po = (size_t)img * 1024 + (size_t)(by * 2 + sh) * 32 + (bx * 2 + sw);
            (Xp + OFF4)[po] = a; (Yp + OFF4)[po] = b;
        }
    }

    // ---- vertical blur (4 rows per thread) + epilogue ------------------------
    const float C1 = 1e-4f, C2 = 9e-4f;
    float d_acc = 0.f, cs_acc = 0.f;
    const int ty = tid >> 5, tx = tid & 31;
    const int rbase = ty * 4;
    {
        u64 aMU[4] = {0,0,0,0}, aSP[4] = {0,0,0,0};
#pragma unroll
        for (int k = 0; k < 14; k++) {
            ulonglong2 p = *(const ulonglong2*)&sHB[((rbase + k) * SH_S + tx) * 2];
            u64 v = p.x;
            u64 sp = p.y;
            HTAP(k);
        }
        const int ocol = tx0 + tx;
#pragma unroll
        for (int q = 0; q < 4; q++) {
            int orow = ty0 + rbase + q;
            if (orow < outH && ocol < outH) {
                float mu1, mu2, ess, exy;
                unpack2(aMU[q], mu1, mu2);
                unpack2(aSP[q], ess, exy);
                float mu1sq = mu1 * mu1, mu2sq = mu2 * mu2, mu12 = mu1 * mu2;
                float sig_sum = ess - mu1sq - mu2sq;
                float sig12 = exy - mu12;
                float S1 = __fdividef(2.f * mu12 + C1, mu1sq + mu2sq + C1);
                float S2 = __fdividef(2.f * sig12 + C2, sig_sum + C2);
                float S = fminf(S1 + S2, 2.0f);
                d_acc += sqrt_fast(2.0f - S);
                cs_acc += S2;
            }
        }
    }

    // ---- block reduce + atomic -----------------------------------------------
#pragma unroll
    for (int o = 16; o > 0; o >>= 1) {
        d_acc  += __shfl_down_sync(0xffffffffu, d_acc,  o);
        cs_acc += __shfl_down_sync(0xffffffffu, cs_acc, o);
    }
    if (tx == 0) { red[0][ty] = d_acc; red[1][ty] = cs_acc; }
    __syncthreads();
    if (tid == 0) {
        float ds = 0.f, cs = 0.f;
#pragma unroll
        for (int j = 0; j < 8; j++) { ds += red[0][j]; cs += red[1][j]; }
        atomicAdd(&d_sums[(level * 48 + img) * 2 + 0], ds);
        atomicAdd(&d_sums[(level * 48 + img) * 2 + 1], cs);
    }
}

__global__ void __launch_bounds__(256) ssim_level0_kernel(
    const float* __restrict__ X, const float* __restrict__ Y,
    float* __restrict__ Xp, float* __restrict__ Yp)
{
    const int img = blockIdx.z;
    const float* Xi = X + (size_t)img * 512 * 512;
    const float* Yi = Y + (size_t)img * 512 * 512;
    ssim_tile<true>(Xi, Yi, 512, 0, img, blockIdx.x, blockIdx.y, Xp, Yp);
}

// levels 1..4 in one grid of 4080 blocks
__global__ void __launch_bounds__(256) ssim_rest_kernel(
    const float* __restrict__ Xp, const float* __restrict__ Yp)
{
    int b = blockIdx.x;
    int level, H, nt, off, base;
    if (b < 3072)      { level = 1; H = 256; nt = 8; off = OFF1; base = 0; }
    else if (b < 3840) { level = 2; H = 128; nt = 4; off = OFF2; base = 3072; }
    else if (b < 4032) { level = 3; H = 64;  nt = 2; off = OFF3; base = 3840; }
    else               { level = 4; H = 32;  nt = 1; off = OFF4; base = 4032; }
    int rem = b - base;
    int tiles = nt * nt;
    int img = rem / tiles;
    int t = rem - img * tiles;
    int by = t / nt;
    int bx = t - by * nt;
    const float* Xi = Xp + off + (size_t)img * H * H;
    const float* Yi = Yp + off + (size_t)img * H * H;
    ssim_tile<false>(Xi, Yi, H, level, img, bx, by, nullptr, nullptr);
}

__global__ void final_kernel(float* out, int out_size)
{
    __shared__ float part[2];
    const int i = threadIdx.x;       // 64 threads
    const float wts[5]  = {0.0448f, 0.2856f, 0.3001f, 0.2363f, 0.1333f};
    const float icnt[5] = {1.f/252004.f, 1.f/60516.f, 1.f/13924.f, 1.f/2916.f, 1.f/484.f};
    float v = 0.f;
    if (i < 48) {
        v = 1.f;
#pragma unroll
        for (int l = 0; l < 4; l++) {
            float csm = fmaxf(d_sums[(l * 48 + i) * 2 + 1] * icnt[l], 0.f);
            v *= __powf(csm, wts[l]);
        }
        float dm = fmaxf(d_sums[(4 * 48 + i) * 2 + 0] * icnt[4], 0.f);
        v *= __powf(dm, wts[4]);
    }
    float s = v;
#pragma unroll
    for (int o = 16; o > 0; o >>= 1) s += __shfl_down_sync(0xffffffffu, s, o);
    if ((i & 31) == 0) part[i >> 5] = s;
    __syncthreads();
    if (i == 0) {
        float r = (part[0] + part[1]) * (1.0f / 48.0f);
        for (int k = 0; k < out_size; k++) out[k] = r;
    }
    // restore invariant: d_sums zeroed for the next kernel_launch call
    __syncthreads();
    for (int j = i; j < 480; j += 64) d_sums[j] = 0.f;
}

extern "C" void kernel_launch(void* const* d_in, const int* in_sizes, int n_in,
                              void* d_out, int out_size)
{
    const float* X = (const float*)d_in[0];
    const float* Y = (const float*)d_in[1];
    float* out = (float*)d_out;

    float *Xp = nullptr, *Yp = nullptr;
    cudaGetSymbolAddress((void**)&Xp, d_Xp);
    cudaGetSymbolAddress((void**)&Yp, d_Yp);

    ssim_level0_kernel<<<dim3(16, 16, 48), 256>>>(X, Y, Xp, Yp);
    ssim_rest_kernel<<<4080, 256>>>(Xp, Yp);
    final_kernel<<<1, 64>>>(out, out_size);
}

// round 9
// speedup vs baseline: 1.1723x; 1.1723x over previous
#include <cuda_runtime.h>
#include <math.h>

// ---------------------------------------------------------------------------
// MS-SSIM, 5 levels, 16x3x512x512 fp32 (48 planes).
// 3 launches: ssim_level0 (+ full pool pyramid L1..L4 fused),
// ssim_rest (levels 1..4 in ONE grid), final (parallel combine + re-zero).
// Blur uses 2 packed f32x2 streams: (x,y) and (x^2+y^2, x*y).
// This is the Round-4 champion (131.6us) + verified final-kernel/zero-launch
// improvements only.
// ---------------------------------------------------------------------------

typedef unsigned long long u64;

__device__ __forceinline__ u64 pack2(float lo, float hi) {
    u64 r; asm("mov.b64 %0,{%1,%2};" : "=l"(r) : "f"(lo), "f"(hi)); return r;
}
__device__ __forceinline__ void unpack2(u64 v, float& lo, float& hi) {
    asm("mov.b64 {%0,%1},%2;" : "=f"(lo), "=f"(hi) : "l"(v));
}
__device__ __forceinline__ u64 fma2(u64 a, u64 b, u64 c) {
    u64 d; asm("fma.rn.f32x2 %0,%1,%2,%3;" : "=l"(d) : "l"(a), "l"(b), "l"(c)); return d;
}
__device__ __forceinline__ u64 mul2(u64 a, u64 b) {
    u64 d; asm("mul.rn.f32x2 %0,%1,%2;" : "=l"(d) : "l"(a), "l"(b)); return d;
}
__device__ __forceinline__ u64 add2(u64 a, u64 b) {
    u64 d; asm("add.rn.f32x2 %0,%1,%2;" : "=l"(d) : "l"(a), "l"(b)); return d;
}
__device__ __forceinline__ float sqrt_fast(float x) {
    float r; asm("sqrt.approx.f32 %0,%1;" : "=f"(r) : "f"(x)); return r;
}

#define TW 32
#define TH 32
#define EH 42
#define EW 42
#define SIN_S 44       // u64 stride of input tile
#define SH_S  33       // stride of h-blurred maps

// gaussian(sigma=1.5, 11 taps), normalized
#define G_0 0.00102838f
#define G_1 0.00759876f
#define G_2 0.03600088f
#define G_3 0.10936090f
#define G_4 0.21300530f
#define G_5 0.26601160f

// pooled pyramids (levels 1..4), 48 planes each
// L1: 48*256*256 = 3145728 @0 ; L2 @3145728 ; L3 @3932160 ; L4 @4128768
__device__ __align__(16) float d_Xp[4177920];
__device__ __align__(16) float d_Yp[4177920];
__device__ float d_sums[480];   // [level][img][2]  (zero-init; final re-zeros)

#define OFF1 0
#define OFF2 3145728
#define OFF3 3932160
#define OFF4 4128768

// core tile worker. POOL => level 0 (H=512, also emits L1..L4 pyramid).
template <bool POOL>
__device__ __forceinline__ void ssim_tile(
    const float* __restrict__ Xi, const float* __restrict__ Yi,
    int H, int level, int img, int bx, int by,
    float* __restrict__ Xp, float* __restrict__ Yp)
{
    __shared__ u64 sIN[EH * SIN_S];   // packed (x,y)
    __shared__ u64 sMU[EH * SH_S];    // h-blurred (gx,gy)
    __shared__ u64 sSP[EH * SH_S];    // h-blurred (E[xx+yy], E[xy])
    __shared__ u64 sL2[64];
    __shared__ float red[2][8];

    const int W = H;
    const int outH = H - 10;
    const int tx0 = bx * TW;
    const int ty0 = by * TH;
    const int tid = threadIdx.x;

    const float gg[11] = {G_0,G_1,G_2,G_3,G_4,G_5,G_4,G_3,G_2,G_1,G_0};
    u64 G2r[11];
#pragma unroll
    for (int k = 0; k < 11; k++) G2r[k] = pack2(gg[k], gg[k]);

    // ---- load extended tile, packed (x,y) -----------------------------------
    const bool interior = (tx0 + EW <= W) && (ty0 + EH <= H);
    {
        int r = tid / EW, c = tid - r * EW;
        if (interior) {
            const float* xp = Xi + (size_t)(ty0 + r) * W + (tx0 + c);
            const float* yp = Yi + (size_t)(ty0 + r) * W + (tx0 + c);
            int rr = r, cc = c;
#pragma unroll
            for (int it = 0; it < 7; it++) {
                if (it < 6 || tid < (EH * EW - 6 * 256)) {
                    sIN[rr * SIN_S + cc] = pack2(__ldg(xp), __ldg(yp));
                }
                cc += 4; rr += 6;
                xp += 6 * (size_t)W + 4; yp += 6 * (size_t)W + 4;
                if (cc >= EW) { cc -= EW; rr += 1; xp += W - EW; yp += W - EW; }
            }
        } else {
            for (int i = tid; i < EH * EW; i += 256) {
                int r2 = i / EW, c2 = i - r2 * EW;
                int gr = ty0 + r2; if (gr > H - 1) gr = H - 1;
                int gc = tx0 + c2; if (gc > W - 1) gc = W - 1;
                sIN[r2 * SIN_S + c2] = pack2(Xi[(size_t)gr * W + gc], Yi[(size_t)gr * W + gc]);
            }
        }
    }
    __syncthreads();

    // ---- fused pool pyramid (level 0 only): L1, L2 --------------------------
    if (POOL) {
        const u64 QUARTER = pack2(0.25f, 0.25f);
        const int lane = tid & 31;
        int ph = tid >> 4, pw = tid & 15;
        const u64* p0 = sIN + (ph * 2) * SIN_S + pw * 2;
        u64 v1 = mul2(add2(add2(p0[0], p0[1]), add2(p0[SIN_S], p0[SIN_S + 1])), QUARTER);
        {
            float a, b; unpack2(v1, a, b);
            size_t po = (size_t)img * 65536 + (size_t)(by * 16 + ph) * 256 + (bx * 16 + pw);
            (Xp + OFF1)[po] = a; (Yp + OFF1)[po] = b;
        }
        u64 s2 = add2(v1, __shfl_xor_sync(0xffffffffu, v1, 1));
        s2 = add2(s2, __shfl_xor_sync(0xffffffffu, s2, 16));
        if ((lane & 17) == 0) {
            u64 v2 = mul2(s2, QUARTER);
            int qh = tid >> 5, qw = lane >> 1;
            float a, b; unpack2(v2, a, b);
            size_t po = (size_t)img * 16384 + (size_t)(by * 8 + qh) * 128 + (bx * 8 + qw);
            (Xp + OFF2)[po] = a; (Yp + OFF2)[po] = b;
            sL2[qh * 8 + qw] = v2;
        }
    }

    // ---- horizontal blur: 42 rows x 8 col-groups (4 outputs each) -----------
    {
        auto hblur = [&](int item) {
            int r = item >> 3, c4 = (item & 7) << 2;
            const u64* row = sIN + r * SIN_S + c4;
            u64 aMU[4] = {0,0,0,0}, aSP[4] = {0,0,0,0};
#pragma unroll
            for (int k = 0; k < 14; k++) {
                u64 v = row[k];
                float vx, vy; unpack2(v, vx, vy);
                u64 sp = pack2(fmaf(vx, vx, vy * vy), vx * vy);
#pragma unroll
                for (int q = 0; q < 4; q++) {
                    int t = k - q;
                    if (t >= 0 && t < 11) {
                        aMU[q] = fma2(v,  G2r[t], aMU[q]);
                        aSP[q] = fma2(sp, G2r[t], aSP[q]);
                    }
                }
            }
            int o = r * SH_S + c4;
#pragma unroll
            for (int q = 0; q < 4; q++) {
                sMU[o + q] = aMU[q];
                sSP[o + q] = aSP[q];
            }
        };
        hblur(tid);
        if (tid < EH * 8 - 256) hblur(tid + 256);
    }
    __syncthreads();

    // ---- pyramid tail: L3 + L4 -----------------------------------------------
    if (POOL && tid < 16) {
        const u64 QUARTER = pack2(0.25f, 0.25f);
        int rh = tid >> 2, rw = tid & 3;
        const u64* q0 = sL2 + (rh * 2) * 8 + rw * 2;
        u64 v3 = mul2(add2(add2(q0[0], q0[1]), add2(q0[8], q0[9])), QUARTER);
        {
            float a, b; unpack2(v3, a, b);
            size_t po = (size_t)img * 4096 + (size_t)(by * 4 + rh) * 64 + (bx * 4 + rw);
            (Xp + OFF3)[po] = a; (Yp + OFF3)[po] = b;
        }
        u64 s4 = add2(v3, __shfl_xor_sync(0xffffu, v3, 1));
        s4 = add2(s4, __shfl_xor_sync(0xffffu, s4, 4));
        if ((tid & 5) == 0) {
            u64 v4 = mul2(s4, QUARTER);
            int sh = tid >> 3, sw = (tid >> 1) & 1;
            float a, b; unpack2(v4, a, b);
            size_t po = (size_t)img * 1024 + (size_t)(by * 2 + sh) * 32 + (bx * 2 + sw);
            (Xp + OFF4)[po] = a; (Yp + OFF4)[po] = b;
        }
    }

    // ---- vertical blur (4 rows per thread) + epilogue ------------------------
    const float C1 = 1e-4f, C2 = 9e-4f;
    float d_acc = 0.f, cs_acc = 0.f;
    const int ty = tid >> 5, tx = tid & 31;
    const int rbase = ty * 4;
    {
        u64 aMU[4] = {0,0,0,0}, aSP[4] = {0,0,0,0};
#pragma unroll
        for (int k = 0; k < 14; k++) {
            int row = (rbase + k) * SH_S + tx;
            u64 mu = sMU[row];
            u64 sp = sSP[row];
#pragma unroll
            for (int q = 0; q < 4; q++) {
                int t = k - q;
                if (t >= 0 && t < 11) {
                    aMU[q] = fma2(mu, G2r[t], aMU[q]);
                    aSP[q] = fma2(sp, G2r[t], aSP[q]);
                }
            }
        }
        const int ocol = tx0 + tx;
#pragma unroll
        for (int q = 0; q < 4; q++) {
            int orow = ty0 + rbase + q;
            if (orow < outH && ocol < outH) {
                float mu1, mu2, ess, exy;
                unpack2(aMU[q], mu1, mu2);
                unpack2(aSP[q], ess, exy);
                float mu1sq = mu1 * mu1, mu2sq = mu2 * mu2, mu12 = mu1 * mu2;
                float sig_sum = ess - mu1sq - mu2sq;
                float sig12 = exy - mu12;
                float S1 = __fdividef(2.f * mu12 + C1, mu1sq + mu2sq + C1);
                float S2 = __fdividef(2.f * sig12 + C2, sig_sum + C2);
                float S = fminf(S1 + S2, 2.0f);
                d_acc += sqrt_fast(2.0f - S);
                cs_acc += S2;
            }
        }
    }

    // ---- block reduce + atomic -----------------------------------------------
#pragma unroll
    for (int o = 16; o > 0; o >>= 1) {
        d_acc  += __shfl_down_sync(0xffffffffu, d_acc,  o);
        cs_acc += __shfl_down_sync(0xffffffffu, cs_acc, o);
    }
    if (tx == 0) { red[0][ty] = d_acc; red[1][ty] = cs_acc; }
    __syncthreads();
    if (tid == 0) {
        float ds = 0.f, cs = 0.f;
#pragma unroll
        for (int j = 0; j < 8; j++) { ds += red[0][j]; cs += red[1][j]; }
        atomicAdd(&d_sums[(level * 48 + img) * 2 + 0], ds);
        atomicAdd(&d_sums[(level * 48 + img) * 2 + 1], cs);
    }
}

__global__ void __launch_bounds__(256) ssim_level0_kernel(
    const float* __restrict__ X, const float* __restrict__ Y,
    float* __restrict__ Xp, float* __restrict__ Yp)
{
    const int img = blockIdx.z;
    const float* Xi = X + (size_t)img * 512 * 512;
    const float* Yi = Y + (size_t)img * 512 * 512;
    ssim_tile<true>(Xi, Yi, 512, 0, img, blockIdx.x, blockIdx.y, Xp, Yp);
}

// levels 1..4 in one grid of 4080 blocks
__global__ void __launch_bounds__(256) ssim_rest_kernel(
    const float* __restrict__ Xp, const float* __restrict__ Yp)
{
    int b = blockIdx.x;
    int level, H, nt, off, base;
    if (b < 3072)      { level = 1; H = 256; nt = 8; off = OFF1; base = 0; }
    else if (b < 3840) { level = 2; H = 128; nt = 4; off = OFF2; base = 3072; }
    else if (b < 4032) { level = 3; H = 64;  nt = 2; off = OFF3; base = 3840; }
    else               { level = 4; H = 32;  nt = 1; off = OFF4; base = 4032; }
    int rem = b - base;
    int tiles = nt * nt;
    int img = rem / tiles;
    int t = rem - img * tiles;
    int by = t / nt;
    int bx = t - by * nt;
    const float* Xi = Xp + off + (size_t)img * H * H;
    const float* Yi = Yp + off + (size_t)img * H * H;
    ssim_tile<false>(Xi, Yi, H, level, img, bx, by, nullptr, nullptr);
}

__global__ void final_kernel(float* out, int out_size)
{
    __shared__ float part[2];
    const int i = threadIdx.x;       // 64 threads
    const float wts[5]  = {0.0448f, 0.2856f, 0.3001f, 0.2363f, 0.1333f};
    const float icnt[5] = {1.f/252004.f, 1.f/60516.f, 1.f/13924.f, 1.f/2916.f, 1.f/484.f};
    float v = 0.f;
    if (i < 48) {
        v = 1.f;
#pragma unroll
        for (int l = 0; l < 4; l++) {
            float csm = fmaxf(d_sums[(l * 48 + i) * 2 + 1] * icnt[l], 0.f);
            v *= __powf(csm, wts[l]);
        }
        float dm = fmaxf(d_sums[(4 * 48 + i) * 2 + 0] * icnt[4], 0.f);
        v *= __powf(dm, wts[4]);
    }
    float s = v;
#pragma unroll
    for (int o = 16; o > 0; o >>= 1) s += __shfl_down_sync(0xffffffffu, s, o);
    if ((i & 31) == 0) part[i >> 5] = s;
    __syncthreads();
    if (i == 0) {
        float r = (part[0] + part[1]) * (1.0f / 48.0f);
        for (int k = 0; k < out_size; k++) out[k] = r;
    }
    // restore invariant: d_sums zeroed for the next kernel_launch call
    __syncthreads();
    for (int j = i; j < 480; j += 64) d_sums[j] = 0.f;
}

extern "C" void kernel_launch(void* const* d_in, const int* in_sizes, int n_in,
                              void* d_out, int out_size)
{
    const float* X = (const float*)d_in[0];
    const float* Y = (const float*)d_in[1];
    float* out = (float*)d_out;

    float *Xp = nullptr, *Yp = nullptr;
    cudaGetSymbolAddress((void**)&Xp, d_Xp);
    cudaGetSymbolAddress((void**)&Yp, d_Yp);

    ssim_level0_kernel<<<dim3(16, 16, 48), 256>>>(X, Y, Xp, Yp);
    ssim_rest_kernel<<<4080, 256>>>(Xp, Yp);
    final_kernel<<<1, 64>>>(out, out_size);
}